// round 2
// baseline (speedup 1.0000x reference)
#include <cuda_runtime.h>
#include <cuda_bf16.h>
#include <cstdint>

// VQ cdist: out[n,k] = sqrt(max(||x_n||^2 + ||e_k||^2 - 2 x_n.e_k, 0))
// N=65536, K=1024, D=64 (D hardcoded; N,K derived from in_sizes).
//
// 128x128 output tile per CTA, 256 threads (8 warps, 4x2 warp grid,
// 32x64 warp tile). fp32 -> bf16 conversion into padded smem; exact fp32
// squared norms computed during the load. mma.sync.m16n8k16 bf16 for the
// cross term, fused sqrt epilogue, float2 stores.
//
// R1 fix: B fragment uses NON-transposed ldmatrix — Bs is [n][k] with k
// contiguous, which already matches the mma.row.col B fragment layout
// (thread l holds k-pair l%4 at n = l>>2).

#define BM 128
#define BN 128
#define PAD_LD 72   // bf16 elements per smem row (64 + 8 pad -> 144B rows, 16B aligned)

__device__ __forceinline__ void ldsm_x4(uint32_t& r0, uint32_t& r1, uint32_t& r2, uint32_t& r3, uint32_t addr) {
    asm volatile("ldmatrix.sync.aligned.m8n8.x4.shared.b16 {%0,%1,%2,%3}, [%4];"
                 : "=r"(r0), "=r"(r1), "=r"(r2), "=r"(r3) : "r"(addr));
}

__device__ __forceinline__ void mma_bf16(float* c, const uint32_t* a, const uint32_t* b) {
    asm volatile("mma.sync.aligned.m16n8k16.row.col.f32.bf16.bf16.f32 "
                 "{%0,%1,%2,%3}, {%4,%5,%6,%7}, {%8,%9}, {%0,%1,%2,%3};"
                 : "+f"(c[0]), "+f"(c[1]), "+f"(c[2]), "+f"(c[3])
                 : "r"(a[0]), "r"(a[1]), "r"(a[2]), "r"(a[3]), "r"(b[0]), "r"(b[1]));
}

__global__ __launch_bounds__(256)
void vq_cdist_kernel(const float* __restrict__ X,   // [N, 64]
                     const float* __restrict__ E,   // [K, 64]
                     float* __restrict__ out,       // [N, K]
                     int Kdim) {
    __shared__ __align__(16) __nv_bfloat16 As[BM][PAD_LD];
    __shared__ __align__(16) __nv_bfloat16 Bs[BN][PAD_LD];
    __shared__ float xsq[BM];
    __shared__ float esq[BN];

    const int tid  = threadIdx.x;
    const int lane = tid & 31;
    const int wid  = tid >> 5;
    const int m0 = blockIdx.y * BM;
    const int n0 = blockIdx.x * BN;

    // ---- Load A tile (fp32 -> bf16), compute row squared norms ----
    {
        const int row   = tid >> 1;            // 0..127, 2 threads per row
        const int cbase = (tid & 1) * 32;      // each thread: 32 consecutive floats
        const float4* src = reinterpret_cast<const float4*>(X + (size_t)(m0 + row) * 64 + cbase);
        float ss = 0.f;
        #pragma unroll
        for (int i = 0; i < 8; i++) {
            float4 v = src[i];
            ss += v.x * v.x + v.y * v.y + v.z * v.z + v.w * v.w;
            __nv_bfloat162 p0 = __floats2bfloat162_rn(v.x, v.y);
            __nv_bfloat162 p1 = __floats2bfloat162_rn(v.z, v.w);
            uint2 pk;
            pk.x = *reinterpret_cast<uint32_t*>(&p0);
            pk.y = *reinterpret_cast<uint32_t*>(&p1);
            *reinterpret_cast<uint2*>(&As[row][cbase + i * 4]) = pk;
        }
        ss += __shfl_xor_sync(0xffffffffu, ss, 1);
        if ((tid & 1) == 0) xsq[row] = ss;
    }
    // ---- Load B tile (embeddings), compute col squared norms ----
    {
        const int row   = tid >> 1;
        const int cbase = (tid & 1) * 32;
        const float4* src = reinterpret_cast<const float4*>(E + (size_t)(n0 + row) * 64 + cbase);
        float ss = 0.f;
        #pragma unroll
        for (int i = 0; i < 8; i++) {
            float4 v = src[i];
            ss += v.x * v.x + v.y * v.y + v.z * v.z + v.w * v.w;
            __nv_bfloat162 p0 = __floats2bfloat162_rn(v.x, v.y);
            __nv_bfloat162 p1 = __floats2bfloat162_rn(v.z, v.w);
            uint2 pk;
            pk.x = *reinterpret_cast<uint32_t*>(&p0);
            pk.y = *reinterpret_cast<uint32_t*>(&p1);
            *reinterpret_cast<uint2*>(&Bs[row][cbase + i * 4]) = pk;
        }
        ss += __shfl_xor_sync(0xffffffffu, ss, 1);
        if ((tid & 1) == 0) esq[row] = ss;
    }
    __syncthreads();

    // ---- Warp tiling: 4 warps along M (32 rows each), 2 along N (64 cols each) ----
    const int wm = (wid & 3) * 32;
    const int wn = (wid >> 2) * 64;

    float acc[2][8][4];
    #pragma unroll
    for (int mt = 0; mt < 2; mt++)
        #pragma unroll
        for (int nt = 0; nt < 8; nt++)
            #pragma unroll
            for (int i = 0; i < 4; i++) acc[mt][nt][i] = 0.f;

    const uint32_t a_base = (uint32_t)__cvta_generic_to_shared(&As[0][0]);
    const uint32_t b_base = (uint32_t)__cvta_generic_to_shared(&Bs[0][0]);

    #pragma unroll
    for (int ks = 0; ks < 4; ks++) {
        const int kc = ks * 16;

        uint32_t a_frag[2][4];
        #pragma unroll
        for (int mt = 0; mt < 2; mt++) {
            int r = wm + mt * 16 + (lane & 15);
            int c = kc + ((lane >> 4) << 3);
            uint32_t addr = a_base + (uint32_t)(r * PAD_LD + c) * 2u;
            ldsm_x4(a_frag[mt][0], a_frag[mt][1], a_frag[mt][2], a_frag[mt][3], addr);
        }

        uint32_t b_frag[8][2];
        #pragma unroll
        for (int np = 0; np < 4; np++) {  // each x4 covers two 8-col n-tiles (16 n rows)
            // lanes 0-7:  n 0-7,  k 0-7   -> matrix0 = b_frag[even][0]
            // lanes 8-15: n 0-7,  k 8-15  -> matrix1 = b_frag[even][1]
            // lanes 16-23: n 8-15, k 0-7  -> matrix2 = b_frag[odd][0]
            // lanes 24-31: n 8-15, k 8-15 -> matrix3 = b_frag[odd][1]
            int nr = wn + np * 16 + ((lane >> 4) & 1) * 8 + (lane & 7);
            int kk = kc + ((lane >> 3) & 1) * 8;
            uint32_t addr = b_base + (uint32_t)(nr * PAD_LD + kk) * 2u;
            uint32_t r0, r1, r2, r3;
            ldsm_x4(r0, r1, r2, r3, addr);
            b_frag[np * 2][0] = r0; b_frag[np * 2][1] = r1;
            b_frag[np * 2 + 1][0] = r2; b_frag[np * 2 + 1][1] = r3;
        }

        #pragma unroll
        for (int mt = 0; mt < 2; mt++)
            #pragma unroll
            for (int nt = 0; nt < 8; nt++)
                mma_bf16(acc[mt][nt], a_frag[mt], b_frag[nt]);
    }

    // ---- Epilogue: dist = sqrt(max(xsq + esq - 2*cross, 0)), float2 stores ----
    const int rbase = wm + (lane >> 2);
    #pragma unroll
    for (int mt = 0; mt < 2; mt++) {
        const int lr0 = rbase + mt * 16;      // local row for c0,c1
        const int lr1 = lr0 + 8;              // local row for c2,c3
        const float xsa = xsq[lr0];
        const float xsb = xsq[lr1];
        float* o0 = out + (size_t)(m0 + lr0) * Kdim + n0;
        float* o1 = out + (size_t)(m0 + lr1) * Kdim + n0;
        #pragma unroll
        for (int nt = 0; nt < 8; nt++) {
            const int c = wn + nt * 8 + (lane & 3) * 2;
            const float e0 = esq[c];
            const float e1 = esq[c + 1];
            float2 v0, v1;
            v0.x = sqrtf(fmaxf(xsa + e0 - 2.0f * acc[mt][nt][0], 0.f));
            v0.y = sqrtf(fmaxf(xsa + e1 - 2.0f * acc[mt][nt][1], 0.f));
            v1.x = sqrtf(fmaxf(xsb + e0 - 2.0f * acc[mt][nt][2], 0.f));
            v1.y = sqrtf(fmaxf(xsb + e1 - 2.0f * acc[mt][nt][3], 0.f));
            *reinterpret_cast<float2*>(o0 + c) = v0;
            *reinterpret_cast<float2*>(o1 + c) = v1;
        }
    }
}

extern "C" void kernel_launch(void* const* d_in, const int* in_sizes, int n_in,
                              void* d_out, int out_size) {
    const float* X = (const float*)d_in[0];   // inputs [N, 64]
    const float* E = (const float*)d_in[1];   // embeddings [K, 64]
    float* out = (float*)d_out;               // [N, K] fp32

    const int N = in_sizes[0] / 64;
    const int K = in_sizes[1] / 64;

    // grid.x = K tiles (8): consecutive blocks share the same A row-block -> L2 reuse
    dim3 grid(K / BN, N / BM);
    vq_cdist_kernel<<<grid, 256>>>(X, E, out, K);
}

// round 3
// speedup vs baseline: 1.3691x; 1.3691x over previous
#include <cuda_runtime.h>
#include <cuda_bf16.h>
#include <cstdint>

// VQ cdist: out[n,k] = sqrt(max(||x_n||^2 + ||e_k||^2 - 2 x_n.e_k, 0))
// N=65536, K=1024, D=64.
//
// 128x128 output tile per CTA, 256 threads (8 warps, 4x2 warp grid, 32x64
// warp tiles), mma.sync m16n8k16 bf16 cross term + exact fp32 norms.
//
// R3: (1) warp-contiguous float4 LDG (4 wavefronts/instr instead of 32),
//     norms via shfl reduction over 16-lane groups;
//     (2) column-permuted B smem placement so each thread owns 4 contiguous
//     output columns -> STG.128 epilogue (half the store instructions).

#define BM 128
#define BN 128
#define PAD_LD 72   // bf16 elements per smem row (64 + 8 pad -> 144B rows)

__device__ __forceinline__ void ldsm_x4(uint32_t& r0, uint32_t& r1, uint32_t& r2, uint32_t& r3, uint32_t addr) {
    asm volatile("ldmatrix.sync.aligned.m8n8.x4.shared.b16 {%0,%1,%2,%3}, [%4];"
                 : "=r"(r0), "=r"(r1), "=r"(r2), "=r"(r3) : "r"(addr));
}

__device__ __forceinline__ void mma_bf16(float* c, const uint32_t* a, const uint32_t* b) {
    asm volatile("mma.sync.aligned.m16n8k16.row.col.f32.bf16.bf16.f32 "
                 "{%0,%1,%2,%3}, {%4,%5,%6,%7}, {%8,%9}, {%0,%1,%2,%3};"
                 : "+f"(c[0]), "+f"(c[1]), "+f"(c[2]), "+f"(c[3])
                 : "r"(a[0]), "r"(a[1]), "r"(a[2]), "r"(a[3]), "r"(b[0]), "r"(b[1]));
}

// logical col l (within 16-group) -> physical smem slot, so that mma fragment
// ownership {2t, 2t+1, 2t+8, 2t+9} (phys) maps to logical {4t..4t+3}.
__device__ __forceinline__ int bperm(int l) {
    int t = l >> 2, j = l & 3;
    return 2 * t + (j & 1) + ((j >> 1) << 3);
}

__global__ __launch_bounds__(256)
void vq_cdist_kernel(const float* __restrict__ X,   // [N, 64]
                     const float* __restrict__ E,   // [K, 64]
                     float* __restrict__ out,       // [N, K]
                     int Kdim) {
    __shared__ __align__(16) __nv_bfloat16 As[BM][PAD_LD];
    __shared__ __align__(16) __nv_bfloat16 Bs[BN][PAD_LD];
    __shared__ __align__(16) float xsq[BM];
    __shared__ __align__(16) float esq[BN];

    const int tid  = threadIdx.x;
    const int lane = tid & 31;
    const int wid  = tid >> 5;
    const int m0 = blockIdx.y * BM;
    const int n0 = blockIdx.x * BN;

    // ---- Load A tile: warp-contiguous float4, fp32->bf16, exact norms ----
    {
        const float4* Xv = reinterpret_cast<const float4*>(X + (size_t)m0 * 64);
        #pragma unroll
        for (int i = 0; i < 8; i++) {
            const int f   = tid + i * 256;   // float4 index in tile (16 per row)
            const int row = f >> 4;
            const int c4  = f & 15;
            float4 v = Xv[f];
            float ss = v.x * v.x + v.y * v.y + v.z * v.z + v.w * v.w;
            __nv_bfloat162 p0 = __floats2bfloat162_rn(v.x, v.y);
            __nv_bfloat162 p1 = __floats2bfloat162_rn(v.z, v.w);
            uint2 pk;
            pk.x = *reinterpret_cast<uint32_t*>(&p0);
            pk.y = *reinterpret_cast<uint32_t*>(&p1);
            *reinterpret_cast<uint2*>(&As[row][c4 * 4]) = pk;
            // reduce over the 16 lanes sharing this row
            ss += __shfl_xor_sync(0xffffffffu, ss, 1);
            ss += __shfl_xor_sync(0xffffffffu, ss, 2);
            ss += __shfl_xor_sync(0xffffffffu, ss, 4);
            ss += __shfl_xor_sync(0xffffffffu, ss, 8);
            if ((lane & 15) == 0) xsq[row] = ss;
        }
    }
    // ---- Load B tile: same pattern + column permutation ----
    {
        const float4* Ev = reinterpret_cast<const float4*>(E + (size_t)n0 * 64);
        #pragma unroll
        for (int i = 0; i < 8; i++) {
            const int f    = tid + i * 256;
            const int lrow = f >> 4;                       // logical local col
            const int c4   = f & 15;
            const int prow = (lrow & ~15) | bperm(lrow & 15);
            float4 v = Ev[f];
            float ss = v.x * v.x + v.y * v.y + v.z * v.z + v.w * v.w;
            __nv_bfloat162 p0 = __floats2bfloat162_rn(v.x, v.y);
            __nv_bfloat162 p1 = __floats2bfloat162_rn(v.z, v.w);
            uint2 pk;
            pk.x = *reinterpret_cast<uint32_t*>(&p0);
            pk.y = *reinterpret_cast<uint32_t*>(&p1);
            *reinterpret_cast<uint2*>(&Bs[prow][c4 * 4]) = pk;
            ss += __shfl_xor_sync(0xffffffffu, ss, 1);
            ss += __shfl_xor_sync(0xffffffffu, ss, 2);
            ss += __shfl_xor_sync(0xffffffffu, ss, 4);
            ss += __shfl_xor_sync(0xffffffffu, ss, 8);
            if ((lane & 15) == 0) esq[lrow] = ss;          // logical index
        }
    }
    __syncthreads();

    // ---- Warp tiling: 4 warps along M (32 rows), 2 along N (64 cols) ----
    const int wm = (wid & 3) * 32;
    const int wn = (wid >> 2) * 64;

    float acc[2][8][4];
    #pragma unroll
    for (int mt = 0; mt < 2; mt++)
        #pragma unroll
        for (int nt = 0; nt < 8; nt++)
            #pragma unroll
            for (int i = 0; i < 4; i++) acc[mt][nt][i] = 0.f;

    const uint32_t a_base = (uint32_t)__cvta_generic_to_shared(&As[0][0]);
    const uint32_t b_base = (uint32_t)__cvta_generic_to_shared(&Bs[0][0]);

    #pragma unroll
    for (int ks = 0; ks < 4; ks++) {
        const int kc = ks * 16;

        uint32_t a_frag[2][4];
        #pragma unroll
        for (int mt = 0; mt < 2; mt++) {
            int r = wm + mt * 16 + (lane & 15);
            int c = kc + ((lane >> 4) << 3);
            uint32_t addr = a_base + (uint32_t)(r * PAD_LD + c) * 2u;
            ldsm_x4(a_frag[mt][0], a_frag[mt][1], a_frag[mt][2], a_frag[mt][3], addr);
        }

        uint32_t b_frag[8][2];
        #pragma unroll
        for (int np = 0; np < 4; np++) {  // each x4 covers two 8-col (physical) n-tiles
            int nr = wn + np * 16 + ((lane >> 4) & 1) * 8 + (lane & 7);
            int kk = kc + ((lane >> 3) & 1) * 8;
            uint32_t addr = b_base + (uint32_t)(nr * PAD_LD + kk) * 2u;
            uint32_t r0, r1, r2, r3;
            ldsm_x4(r0, r1, r2, r3, addr);
            b_frag[np * 2][0] = r0; b_frag[np * 2][1] = r1;
            b_frag[np * 2 + 1][0] = r2; b_frag[np * 2 + 1][1] = r3;
        }

        #pragma unroll
        for (int mt = 0; mt < 2; mt++)
            #pragma unroll
            for (int nt = 0; nt < 8; nt++)
                mma_bf16(acc[mt][nt], a_frag[mt], b_frag[nt]);
    }

    // ---- Epilogue: thread owns 4 contiguous logical cols per 16-group ----
    // acc[mt][2q][0..1] -> logical cols 4t, 4t+1 ; acc[mt][2q+1][0..1] -> 4t+2, 4t+3
    const int rb = wm + (lane >> 2);
    const int t4 = (lane & 3) * 4;
    #pragma unroll
    for (int mt = 0; mt < 2; mt++) {
        const int lr0 = rb + mt * 16;
        const int lr1 = lr0 + 8;
        const float xsa = xsq[lr0];
        const float xsb = xsq[lr1];
        float* o0 = out + (size_t)(m0 + lr0) * Kdim + n0 + wn;
        float* o1 = out + (size_t)(m0 + lr1) * Kdim + n0 + wn;
        #pragma unroll
        for (int q = 0; q < 4; q++) {
            const int c = q * 16 + t4;
            const float4 es = *reinterpret_cast<const float4*>(&esq[wn + c]);
            float4 v0, v1;
            v0.x = sqrtf(fmaxf(xsa + es.x - 2.0f * acc[mt][2*q][0],   0.f));
            v0.y = sqrtf(fmaxf(xsa + es.y - 2.0f * acc[mt][2*q][1],   0.f));
            v0.z = sqrtf(fmaxf(xsa + es.z - 2.0f * acc[mt][2*q+1][0], 0.f));
            v0.w = sqrtf(fmaxf(xsa + es.w - 2.0f * acc[mt][2*q+1][1], 0.f));
            v1.x = sqrtf(fmaxf(xsb + es.x - 2.0f * acc[mt][2*q][2],   0.f));
            v1.y = sqrtf(fmaxf(xsb + es.y - 2.0f * acc[mt][2*q][3],   0.f));
            v1.z = sqrtf(fmaxf(xsb + es.z - 2.0f * acc[mt][2*q+1][2], 0.f));
            v1.w = sqrtf(fmaxf(xsb + es.w - 2.0f * acc[mt][2*q+1][3], 0.f));
            *reinterpret_cast<float4*>(o0 + c) = v0;
            *reinterpret_cast<float4*>(o1 + c) = v1;
        }
    }
}

extern "C" void kernel_launch(void* const* d_in, const int* in_sizes, int n_in,
                              void* d_out, int out_size) {
    const float* X = (const float*)d_in[0];   // inputs [N, 64]
    const float* E = (const float*)d_in[1];   // embeddings [K, 64]
    float* out = (float*)d_out;               // [N, K] fp32

    const int N = in_sizes[0] / 64;
    const int K = in_sizes[1] / 64;

    dim3 grid(K / BN, N / BM);
    vq_cdist_kernel<<<grid, 256>>>(X, E, out, K);
}